// round 16
// baseline (speedup 1.0000x reference)
#include <cuda_runtime.h>
#include <cstdint>

// HarmonicPolynomialR3Generator — R16: R15 + ONE change: stages 4-7 cob moved
// from smem to gmem __ldg (same [3PL][16-float-column] j-slot layout, 64B
// columns inside one 128B line). Rationale: LDS charges crossbar per
// lane-byte (LDS.128 broadcast = 4 cyc) while LDG L1-hits charge per unique
// line (~1 wavefront) — R9->R10 showed this won for stages 8-10.
// Everything else identical to R15: P=4, J=4, TM {2,2,4,4,4,4,6,6,6},
// warp-local pipeline, scalar copies, BLOCK=192, 4 CTAs/SM, regs 80.

typedef unsigned long long ull;

__device__ __forceinline__ ull ffma2(ull a, ull b, ull c) {
    ull d; asm("fma.rn.f32x2 %0, %1, %2, %3;" : "=l"(d) : "l"(a), "l"(b), "l"(c)); return d;
}
__device__ __forceinline__ ull fmul2(ull a, ull b) {
    ull d; asm("mul.rn.f32x2 %0, %1, %2;" : "=l"(d) : "l"(a), "l"(b)); return d;
}
__device__ __forceinline__ ull pack2(float lo, float hi) {
    ull d; asm("mov.b64 %0, {%1, %2};" : "=l"(d) : "f"(lo), "f"(hi)); return d;
}

#define BLOCK 192
#define SLOTS 48
#define TILE  192      // 48 slots * 4 points

// smem cob: only stages 2-3 (tiny, TM=2 float2 path).
#define OFF2   16    // PL=3,  TM=2, SLOTW=2, CS=8
#define OFF3   88    // PL=5,  TM=2, SLOTW=2, CS=8
#define COB_F  208

// gmem cob, mid section: stages 4-7, layout [3PL][16], SLOTW=4, TM=4.
#define GM4    0     // PL=7,  M=21 -> 336 floats
#define GM5    336   // PL=9,  M=27 -> 432
#define GM6    768   // PL=11, M=33 -> 528
#define GM7    1296  // PL=13, M=39 -> 624
#define GM_TOT 1920
// gmem cob, big section: stages 8-10, layout [3PL][32], SLOTW=8, TM=6.
#define GB8    0     // PL=15, M=45 -> 1440 floats
#define GB9    1440  // PL=17, M=51 -> 1632
#define GB10   3072  // PL=19, M=57 -> 1824
#define GB_TOT 4896
__device__ __align__(128) float g_cob_mid[GM_TOT];
__device__ __align__(128) float g_cob_big[GB_TOT];

// exchange per slot (ull): PH0 pairs p at p*22, PH1 at 44+p*22, HDR f1 at
// 88 + p*3; stride 94 (conflict-free slot spread).
#define EXS    94
#define PH0    0
#define PH1    44
#define HDR    88
#define EX_ULL (SLOTS * EXS)
#define SMEM_BYTES (COB_F * 4 + EX_ULL * 8)   // 832 + 36096 = 36928

__global__ void init_cob_big(const float* __restrict__ c4,
                             const float* __restrict__ c5,
                             const float* __restrict__ c6,
                             const float* __restrict__ c7,
                             const float* __restrict__ c8,
                             const float* __restrict__ c9,
                             const float* __restrict__ c10) {
    int tid = blockIdx.x * blockDim.x + threadIdx.x;
    int stride = gridDim.x * blockDim.x;
    // mid section: [3PL][16], TM=4, SLOTW=4
    for (int e = tid; e < GM_TOT; e += stride) {
        int r = e, M, NK;
        const float* c;
        if (r < GM5)      {            M = 21; NK = 9;  c = c4; }
        else if (r < GM6) { r -= GM5;  M = 27; NK = 11; c = c5; }
        else if (r < GM7) { r -= GM6;  M = 33; NK = 13; c = c6; }
        else              { r -= GM7;  M = 39; NK = 15; c = c7; }
        int m = r >> 4;
        int col = r & 15;
        int j = col >> 2;
        int t = col & 3;
        int k = j * 4 + t;
        g_cob_mid[e] = (k < NK) ? c[k * M + m] : 0.0f;
    }
    // big section: [3PL][32], TM=6, SLOTW=8
    for (int e = tid; e < GB_TOT; e += stride) {
        int r = e, M, NK;
        const float* c;
        if (r < GB9)       {            M = 45; NK = 17; c = c8;  }
        else if (r < GB10) { r -= GB9;  M = 51; NK = 19; c = c9;  }
        else               { r -= GB10; M = 57; NK = 21; c = c10; }
        int m = r >> 5;
        int col = r & 31;
        int j = col >> 3;
        int t = col & 7;
        int k = j * 6 + t;
        g_cob_big[e] = (t < 6 && k < NK) ? c[k * M + m] : 0.0f;
    }
}

template <int PL, int TM, int SLOTW>
__device__ __forceinline__ void load_cob(const float* __restrict__ c, float* __restrict__ dst, int tid) {
    constexpr int NK = PL + 2;
    constexpr int M = 3 * PL;
    constexpr int CS = 4 * SLOTW;
    for (int e = tid; e < M * CS; e += BLOCK) {
        int m = e / CS;
        int r = e - m * CS;
        int jj = r / SLOTW;
        int t = r - jj * SLOTW;
        int k = jj * TM + t;
        dst[e] = (t < TM && k < NK) ? c[k * M + m] : 0.0f;
    }
}

// Accumulate one prev index i (3 m's), TM=2, smem cob (stages 2-3).
template <bool FIRST>
__device__ __forceinline__ void acc_i2(const float* __restrict__ col0,
                                       const ull pv[2],
                                       const ull fx[2], const ull fy[2], const ull fz[2],
                                       ull acc[2][2]) {
#pragma unroll
    for (int c = 0; c < 3; ++c) {
        const ull fA = (c == 0) ? fx[0] : (c == 1) ? fy[0] : fz[0];
        const ull fB = (c == 0) ? fx[1] : (c == 1) ? fy[1] : fz[1];
        ull gA = fmul2(pv[0], fA);
        ull gB = fmul2(pv[1], fB);
        const float* col = col0 + c * 8;
        float2 v = *reinterpret_cast<const float2*>(col);
        ull pk[2];
        pk[0] = pack2(v.x, v.x); pk[1] = pack2(v.y, v.y);
#pragma unroll
        for (int t = 0; t < 2; ++t) {
            if (FIRST && c == 0) {
                acc[0][t] = fmul2(pk[t], gA);
                acc[1][t] = fmul2(pk[t], gB);
            } else {
                acc[0][t] = ffma2(pk[t], gA, acc[0][t]);
                acc[1][t] = ffma2(pk[t], gB, acc[1][t]);
            }
        }
    }
}

// TM=4, cob in GLOBAL memory (stages 4-7), CS=16, via __ldg.
template <bool FIRST>
__device__ __forceinline__ void acc_i_m(const float* __restrict__ col0,
                                        const ull pv[2],
                                        const ull fx[2], const ull fy[2], const ull fz[2],
                                        ull acc[2][4]) {
#pragma unroll
    for (int c = 0; c < 3; ++c) {
        const ull fA = (c == 0) ? fx[0] : (c == 1) ? fy[0] : fz[0];
        const ull fB = (c == 0) ? fx[1] : (c == 1) ? fy[1] : fz[1];
        ull gA = fmul2(pv[0], fA);
        ull gB = fmul2(pv[1], fB);
        float4 v = __ldg(reinterpret_cast<const float4*>(col0 + c * 16));
        ull pk[4];
        pk[0] = pack2(v.x, v.x); pk[1] = pack2(v.y, v.y);
        pk[2] = pack2(v.z, v.z); pk[3] = pack2(v.w, v.w);
#pragma unroll
        for (int t = 0; t < 4; ++t) {
            if (FIRST && c == 0) {
                acc[0][t] = fmul2(pk[t], gA);
                acc[1][t] = fmul2(pk[t], gB);
            } else {
                acc[0][t] = ffma2(pk[t], gA, acc[0][t]);
                acc[1][t] = ffma2(pk[t], gB, acc[1][t]);
            }
        }
    }
}

// TM=6, cob in GLOBAL memory (stages 8-10), CS=32, via __ldg.
template <bool FIRST>
__device__ __forceinline__ void acc_i_g(const float* __restrict__ col0,
                                        const ull pv[2],
                                        const ull fx[2], const ull fy[2], const ull fz[2],
                                        ull acc[2][6]) {
#pragma unroll
    for (int c = 0; c < 3; ++c) {
        const ull fA = (c == 0) ? fx[0] : (c == 1) ? fy[0] : fz[0];
        const ull fB = (c == 0) ? fx[1] : (c == 1) ? fy[1] : fz[1];
        ull gA = fmul2(pv[0], fA);
        ull gB = fmul2(pv[1], fB);
        const float* col = col0 + c * 32;
        float4 v = __ldg(reinterpret_cast<const float4*>(col));
        float2 w = __ldg(reinterpret_cast<const float2*>(col + 4));
        ull pk[6];
        pk[0] = pack2(v.x, v.x); pk[1] = pack2(v.y, v.y);
        pk[2] = pack2(v.z, v.z); pk[3] = pack2(v.w, v.w);
        pk[4] = pack2(w.x, w.x); pk[5] = pack2(w.y, w.y);
#pragma unroll
        for (int t = 0; t < 6; ++t) {
            if (FIRST && c == 0) {
                acc[0][t] = fmul2(pk[t], gA);
                acc[1][t] = fmul2(pk[t], gB);
            } else {
                acc[0][t] = ffma2(pk[t], gA, acc[0][t]);
                acc[1][t] = ffma2(pk[t], gB, acc[1][t]);
            }
        }
    }
}

// Smem-cob stage (l = 3 only), TM=2 SLOTW=2.
template <int PL>
__device__ __forceinline__ void stageS(const float* __restrict__ cb, const int j,
                                       const ull fx[2], const ull fy[2], const ull fz[2],
                                       const ull* __restrict__ in0, ull* __restrict__ out0) {
    constexpr int NK = PL + 2;
    ull acc[2][2];
    const float* cbj = cb + j * 2;

    {
        ulonglong2 q0 = *reinterpret_cast<const ulonglong2*>(in0);
        ulonglong2 q1 = *reinterpret_cast<const ulonglong2*>(in0 + 22);
        ull pv[2];
        pv[0] = q0.x; pv[1] = q1.x;
        acc_i2<true>(cbj, pv, fx, fy, fz, acc);
        pv[0] = q0.y; pv[1] = q1.y;
        acc_i2<false>(cbj + 3 * 8, pv, fx, fy, fz, acc);
    }
#pragma unroll
    for (int ii = 2; ii + 1 < PL; ii += 2) {
        ulonglong2 q0 = *reinterpret_cast<const ulonglong2*>(in0 + ii);
        ulonglong2 q1 = *reinterpret_cast<const ulonglong2*>(in0 + 22 + ii);
        ull pv[2];
        pv[0] = q0.x; pv[1] = q1.x;
        acc_i2<false>(cbj + 3 * ii * 8, pv, fx, fy, fz, acc);
        pv[0] = q0.y; pv[1] = q1.y;
        acc_i2<false>(cbj + 3 * (ii + 1) * 8, pv, fx, fy, fz, acc);
    }
    {
        ull pv[2];
        pv[0] = in0[PL - 1];
        pv[1] = in0[22 + PL - 1];
        acc_i2<false>(cbj + 3 * (PL - 1) * 8, pv, fx, fy, fz, acc);
    }
#pragma unroll
    for (int t = 0; t < 2; ++t) {
        const int k = j * 2 + t;
        if (k < NK) {
            out0[k] = acc[0][t];
            out0[22 + k] = acc[1][t];
        }
    }
}

// Gmem-cob stage, TM=4 CS=16 (stages 4-7).
template <int PL>
__device__ __forceinline__ void stageM(const float* __restrict__ gb, const int j,
                                       const ull fx[2], const ull fy[2], const ull fz[2],
                                       const ull* __restrict__ in0, ull* __restrict__ out0) {
    constexpr int NK = PL + 2;
    ull acc[2][4];
    const float* cbj = gb + j * 4;

    {
        ulonglong2 q0 = *reinterpret_cast<const ulonglong2*>(in0);
        ulonglong2 q1 = *reinterpret_cast<const ulonglong2*>(in0 + 22);
        ull pv[2];
        pv[0] = q0.x; pv[1] = q1.x;
        acc_i_m<true>(cbj, pv, fx, fy, fz, acc);
        pv[0] = q0.y; pv[1] = q1.y;
        acc_i_m<false>(cbj + 3 * 16, pv, fx, fy, fz, acc);
    }
#pragma unroll
    for (int ii = 2; ii + 1 < PL; ii += 2) {
        ulonglong2 q0 = *reinterpret_cast<const ulonglong2*>(in0 + ii);
        ulonglong2 q1 = *reinterpret_cast<const ulonglong2*>(in0 + 22 + ii);
        ull pv[2];
        pv[0] = q0.x; pv[1] = q1.x;
        acc_i_m<false>(cbj + 3 * ii * 16, pv, fx, fy, fz, acc);
        pv[0] = q0.y; pv[1] = q1.y;
        acc_i_m<false>(cbj + 3 * (ii + 1) * 16, pv, fx, fy, fz, acc);
    }
    {
        ull pv[2];
        pv[0] = in0[PL - 1];
        pv[1] = in0[22 + PL - 1];
        acc_i_m<false>(cbj + 3 * (PL - 1) * 16, pv, fx, fy, fz, acc);
    }
#pragma unroll
    for (int t = 0; t < 4; ++t) {
        const int k = j * 4 + t;
        if (k < NK) {
            out0[k] = acc[0][t];
            out0[22 + k] = acc[1][t];
        }
    }
}

// Gmem-cob stage, TM=6 CS=32 (stages 8-10).
template <int PL>
__device__ __forceinline__ void stageG(const float* __restrict__ gb, const int j,
                                       const ull fx[2], const ull fy[2], const ull fz[2],
                                       const ull* __restrict__ in0, ull* __restrict__ out0) {
    constexpr int NK = PL + 2;
    ull acc[2][6];
    const float* cbj = gb + j * 8;

    {
        ulonglong2 q0 = *reinterpret_cast<const ulonglong2*>(in0);
        ulonglong2 q1 = *reinterpret_cast<const ulonglong2*>(in0 + 22);
        ull pv[2];
        pv[0] = q0.x; pv[1] = q1.x;
        acc_i_g<true>(cbj, pv, fx, fy, fz, acc);
        pv[0] = q0.y; pv[1] = q1.y;
        acc_i_g<false>(cbj + 3 * 32, pv, fx, fy, fz, acc);
    }
#pragma unroll
    for (int ii = 2; ii + 1 < PL; ii += 2) {
        ulonglong2 q0 = *reinterpret_cast<const ulonglong2*>(in0 + ii);
        ulonglong2 q1 = *reinterpret_cast<const ulonglong2*>(in0 + 22 + ii);
        ull pv[2];
        pv[0] = q0.x; pv[1] = q1.x;
        acc_i_g<false>(cbj + 3 * ii * 32, pv, fx, fy, fz, acc);
        pv[0] = q0.y; pv[1] = q1.y;
        acc_i_g<false>(cbj + 3 * (ii + 1) * 32, pv, fx, fy, fz, acc);
    }
    {
        ull pv[2];
        pv[0] = in0[PL - 1];
        pv[1] = in0[22 + PL - 1];
        acc_i_g<false>(cbj + 3 * (PL - 1) * 32, pv, fx, fy, fz, acc);
    }
#pragma unroll
    for (int t = 0; t < 6; ++t) {
        const int k = j * 6 + t;
        if (k < NK) {
            out0[k] = acc[0][t];
            out0[22 + k] = acc[1][t];
        }
    }
}

// Per-warp copy: warp owns slots [wslot0, wslot0+8) -> 16 pairs (32 points).
template <int NK, int OUTOFF, int POFF>
__device__ __forceinline__ void copy_stage_w(const ull* __restrict__ exu,
                                             float* __restrict__ out,
                                             int base, int rem, int wslot0, int lane) {
    constexpr int TOT = 16 * NK;
#pragma unroll
    for (int i = 0; i < (TOT + 31) / 32; ++i) {
        int e = lane + 32 * i;
        if (e < TOT) {
            int q = e / NK;
            int k = e - q * NK;
            int s8 = q & 7;
            int p = q >> 3;
            ull v = exu[(wslot0 + s8) * EXS + POFF + p * 22 + k];
            float lo, hi;
            asm("mov.b64 {%0, %1}, %2;" : "=f"(lo), "=f"(hi) : "l"(v));
            int ptlo = wslot0 + s8 + 96 * p;
            int pthi = ptlo + 48;
            if (ptlo < rem) __stcs(out + (size_t)(base + ptlo) * 121 + OUTOFF + k, lo);
            if (pthi < rem) __stcs(out + (size_t)(base + pthi) * 121 + OUTOFF + k, hi);
        }
    }
}

__device__ __forceinline__ void copy_hdr_w(const ull* __restrict__ exu,
                                           float* __restrict__ out,
                                           int base, int rem, int wslot0, int lane) {
#pragma unroll
    for (int i = 0; i < 2; ++i) {
        int e = lane + 32 * i;
        int q = e >> 2;
        int k = e & 3;
        int s8 = q & 7;
        int p = q >> 3;
        float lo = 1.0f, hi = 1.0f;
        if (k != 0) {
            ull v = exu[(wslot0 + s8) * EXS + HDR + p * 3 + (k - 1)];
            asm("mov.b64 {%0, %1}, %2;" : "=f"(lo), "=f"(hi) : "l"(v));
        }
        int ptlo = wslot0 + s8 + 96 * p;
        int pthi = ptlo + 48;
        if (ptlo < rem) __stcs(out + (size_t)(base + ptlo) * 121 + k, lo);
        if (pthi < rem) __stcs(out + (size_t)(base + pthi) * 121 + k, hi);
    }
}

__global__ void __launch_bounds__(BLOCK, 4)
harmonic_kernel(const float* __restrict__ pts,
                const float* __restrict__ c1, const float* __restrict__ c2,
                const float* __restrict__ c3,
                float* __restrict__ out, int N) {
    extern __shared__ float dynf[];
    float* scob = dynf;
    ull* ex = reinterpret_cast<ull*>(dynf + COB_F);

    const int tid = threadIdx.x;
    const int slot = tid >> 2;
    const int j = tid & 3;
    const int lane = tid & 31;
    const int wslot0 = (tid >> 5) * 8;

    if (tid < 16) scob[tid] = (tid < 9) ? c1[tid] : 0.0f;
    load_cob<3, 2, 2>(c2, scob + OFF2, tid);
    load_cob<5, 2, 2>(c3, scob + OFF3, tid);
    __syncthreads();

    const int base = blockIdx.x * TILE;
    int rem = N - base; if (rem > TILE) rem = TILE;

    // 4 points: pair p covers (slot + 96p, slot + 96p + 48)
    ull px[2], py[2], pz[2];
#pragma unroll
    for (int p = 0; p < 2; ++p) {
        int plo = base + slot + 96 * p;
        int phi = plo + 48;
        float xl = 0.f, yl = 0.f, zl = 0.f, xh = 0.f, yh = 0.f, zh = 0.f;
        if (plo < N) { xl = pts[3 * plo]; yl = pts[3 * plo + 1]; zl = pts[3 * plo + 2]; }
        if (phi < N) { xh = pts[3 * phi]; yh = pts[3 * phi + 1]; zh = pts[3 * phi + 2]; }
        px[p] = pack2(xl, xh); py[p] = pack2(yl, yh); pz[p] = pack2(zl, zh);
    }

    ull k0 = pack2(scob[0], scob[0]), k1 = pack2(scob[1], scob[1]), k2 = pack2(scob[2], scob[2]);
    ull k3 = pack2(scob[3], scob[3]), k4 = pack2(scob[4], scob[4]), k5 = pack2(scob[5], scob[5]);
    ull k6 = pack2(scob[6], scob[6]), k7 = pack2(scob[7], scob[7]), k8 = pack2(scob[8], scob[8]);

    ull fx[2], fy[2], fz[2];
#pragma unroll
    for (int p = 0; p < 2; ++p) {
        fx[p] = ffma2(k0, px[p], ffma2(k1, py[p], fmul2(k2, pz[p])));
        fy[p] = ffma2(k3, px[p], ffma2(k4, py[p], fmul2(k5, pz[p])));
        fz[p] = ffma2(k6, px[p], ffma2(k7, py[p], fmul2(k8, pz[p])));
    }

    ull* es = ex + slot * EXS;
    if (j == 0) {
#pragma unroll
        for (int p = 0; p < 2; ++p) {
            es[HDR + p * 3 + 0] = fx[p];
            es[HDR + p * 3 + 1] = fy[p];
            es[HDR + p * 3 + 2] = fz[p];
        }
    }

    // ---- stage l=2 (prev = f1 in registers) -> PH0 ----
    {
        ull acc[2][2];
        const float* cbj = scob + OFF2 + j * 2;
        acc_i2<true >(cbj,      fx, fx, fy, fz, acc);
        acc_i2<false>(cbj + 24, fy, fx, fy, fz, acc);
        acc_i2<false>(cbj + 48, fz, fx, fy, fz, acc);
#pragma unroll
        for (int t = 0; t < 2; ++t) {
            int k = j * 2 + t;
            if (k < 5) { es[PH0 + k] = acc[0][t]; es[PH0 + 22 + k] = acc[1][t]; }
        }
    }
    __syncwarp();

    copy_hdr_w(ex, out, base, rem, wslot0, lane);
    copy_stage_w<5, 4, PH0>(ex, out, base, rem, wslot0, lane);
    stageS<5>(scob + OFF3, j, fx, fy, fz, es + PH0, es + PH1);
    __syncwarp();

    copy_stage_w<7, 9, PH1>(ex, out, base, rem, wslot0, lane);
    stageM<7>(g_cob_mid + GM4, j, fx, fy, fz, es + PH1, es + PH0);
    __syncwarp();

    copy_stage_w<9, 16, PH0>(ex, out, base, rem, wslot0, lane);
    stageM<9>(g_cob_mid + GM5, j, fx, fy, fz, es + PH0, es + PH1);
    __syncwarp();

    copy_stage_w<11, 25, PH1>(ex, out, base, rem, wslot0, lane);
    stageM<11>(g_cob_mid + GM6, j, fx, fy, fz, es + PH1, es + PH0);
    __syncwarp();

    copy_stage_w<13, 36, PH0>(ex, out, base, rem, wslot0, lane);
    stageM<13>(g_cob_mid + GM7, j, fx, fy, fz, es + PH0, es + PH1);
    __syncwarp();

    copy_stage_w<15, 49, PH1>(ex, out, base, rem, wslot0, lane);
    stageG<15>(g_cob_big + GB8, j, fx, fy, fz, es + PH1, es + PH0);
    __syncwarp();

    copy_stage_w<17, 64, PH0>(ex, out, base, rem, wslot0, lane);
    stageG<17>(g_cob_big + GB9, j, fx, fy, fz, es + PH0, es + PH1);
    __syncwarp();

    copy_stage_w<19, 81, PH1>(ex, out, base, rem, wslot0, lane);
    stageG<19>(g_cob_big + GB10, j, fx, fy, fz, es + PH1, es + PH0);
    __syncwarp();

    copy_stage_w<21, 100, PH0>(ex, out, base, rem, wslot0, lane);
}

extern "C" void kernel_launch(void* const* d_in, const int* in_sizes, int n_in,
                              void* d_out, int out_size) {
    const float* points = (const float*)d_in[0];
    const int N = in_sizes[0] / 3;
    float* out = (float*)d_out;

    cudaFuncSetAttribute(harmonic_kernel,
                         cudaFuncAttributeMaxDynamicSharedMemorySize, SMEM_BYTES);

    init_cob_big<<<20, 256>>>((const float*)d_in[4], (const float*)d_in[5],
                              (const float*)d_in[6], (const float*)d_in[7],
                              (const float*)d_in[8], (const float*)d_in[9],
                              (const float*)d_in[10]);

    const int grid = (N + TILE - 1) / TILE;
    harmonic_kernel<<<grid, BLOCK, SMEM_BYTES>>>(
        points,
        (const float*)d_in[1], (const float*)d_in[2], (const float*)d_in[3],
        out, N);
}

// round 17
// speedup vs baseline: 1.0546x; 1.0546x over previous
#include <cuda_runtime.h>
#include <cstdint>

// HarmonicPolynomialR3Generator — R17: R15 + tight per-stage TM only.
//  TM = {2,2,3,3,4,4,5,5,6} (minimal with 4*TM >= NK) removes k-padding
//  FFMA waste (-5.5% acc work; isolated at -9us from the R12/R13 pair).
//  Everything else identical to R15 (best, 340.5us): P=4, J=4, stages 2-7
//  cob smem, 8-10 gmem __ldg 128B-line columns, warp-local pipeline,
//  scalar coalesced copies, BLOCK=192, 4 CTAs/SM, regs 80.

typedef unsigned long long ull;

__device__ __forceinline__ ull ffma2(ull a, ull b, ull c) {
    ull d; asm("fma.rn.f32x2 %0, %1, %2, %3;" : "=l"(d) : "l"(a), "l"(b), "l"(c)); return d;
}
__device__ __forceinline__ ull fmul2(ull a, ull b) {
    ull d; asm("mul.rn.f32x2 %0, %1, %2;" : "=l"(d) : "l"(a), "l"(b)); return d;
}
__device__ __forceinline__ ull pack2(float lo, float hi) {
    ull d; asm("mov.b64 %0, {%1, %2};" : "=l"(d) : "f"(lo), "f"(hi)); return d;
}

#define BLOCK 192
#define SLOTS 48
#define TILE  192      // 48 slots * 4 points

// small cob smem (float units), [3PL][CS] k-major per-j slots (stages 2-7).
// TM: l2:2 l3:2 l4:3 l5:3 l6:4 l7:4 (SLOTW 2/2/4/4/4/4).
#define OFF2   16    // PL=3,  TM=2, SLOTW=2, CS=8
#define OFF3   88    // PL=5,  TM=2, SLOTW=2, CS=8
#define OFF4   208   // PL=7,  TM=3, SLOTW=4, CS=16
#define OFF5   544   // PL=9,  TM=3, SLOTW=4, CS=16
#define OFF6   976   // PL=11, TM=4, SLOTW=4, CS=16
#define OFF7   1504  // PL=13, TM=4, SLOTW=4, CS=16
#define COB_F  2128

// big cob in gmem: stages 8-10, layout [3PL][32], SLOTW=8. TM: l8:5 l9:5 l10:6.
#define GB8    0      // PL=15, M=45 -> 1440 floats
#define GB9    1440   // PL=17, M=51 -> 1632 floats
#define GB10   3072   // PL=19, M=57 -> 1824 floats
#define GB_TOT 4896
__device__ __align__(128) float g_cob_big[GB_TOT];

// exchange per slot (ull): PH0 pairs p at p*22, PH1 at 44+p*22, HDR f1 at
// 88 + p*3; stride 94 (conflict-free slot spread).
#define EXS    94
#define PH0    0
#define PH1    44
#define HDR    88
#define EX_ULL (SLOTS * EXS)
#define SMEM_BYTES (COB_F * 4 + EX_ULL * 8)   // 8512 + 36096 = 44608

__global__ void init_cob_big(const float* __restrict__ c8,
                             const float* __restrict__ c9,
                             const float* __restrict__ c10) {
    int tid = blockIdx.x * blockDim.x + threadIdx.x;
    for (int e = tid; e < GB_TOT; e += gridDim.x * blockDim.x) {
        int r = e, M, NK, TMs;
        const float* c;
        if (r < GB9)       {            M = 45; NK = 17; TMs = 5; c = c8;  }
        else if (r < GB10) { r -= GB9;  M = 51; NK = 19; TMs = 5; c = c9;  }
        else               { r -= GB10; M = 57; NK = 21; TMs = 6; c = c10; }
        int m = r >> 5;
        int col = r & 31;
        int j = col >> 3;
        int t = col & 7;
        int k = j * TMs + t;
        g_cob_big[e] = (t < TMs && k < NK) ? c[k * M + m] : 0.0f;
    }
}

template <int PL, int TM, int SLOTW>
__device__ __forceinline__ void load_cob(const float* __restrict__ c, float* __restrict__ dst, int tid) {
    constexpr int NK = PL + 2;
    constexpr int M = 3 * PL;
    constexpr int CS = 4 * SLOTW;
    for (int e = tid; e < M * CS; e += BLOCK) {
        int m = e / CS;
        int r = e - m * CS;
        int jj = r / SLOTW;
        int t = r - jj * SLOTW;
        int k = jj * TM + t;
        dst[e] = (t < TM && k < NK) ? c[k * M + m] : 0.0f;
    }
}

// Accumulate one prev index i (3 m's) into TM accumulators x 2 pairs (smem cob).
template <int TM, int SLOTW, int CS, bool FIRST>
__device__ __forceinline__ void acc_i(const float* __restrict__ col0,
                                      const ull pv[2],
                                      const ull fx[2], const ull fy[2], const ull fz[2],
                                      ull acc[2][TM]) {
#pragma unroll
    for (int c = 0; c < 3; ++c) {
        const ull fA = (c == 0) ? fx[0] : (c == 1) ? fy[0] : fz[0];
        const ull fB = (c == 0) ? fx[1] : (c == 1) ? fy[1] : fz[1];
        ull gA = fmul2(pv[0], fA);
        ull gB = fmul2(pv[1], fB);
        const float* col = col0 + c * CS;
        ull pk[TM];
        if constexpr (SLOTW == 2) {
            float2 v = *reinterpret_cast<const float2*>(col);
            pk[0] = pack2(v.x, v.x); pk[1] = pack2(v.y, v.y);
        } else {
            float4 v = *reinterpret_cast<const float4*>(col);
            pk[0] = pack2(v.x, v.x); pk[1] = pack2(v.y, v.y);
            pk[2] = pack2(v.z, v.z);
            if constexpr (TM >= 4) pk[3] = pack2(v.w, v.w);
        }
#pragma unroll
        for (int t = 0; t < TM; ++t) {
            if (FIRST && c == 0) {
                acc[0][t] = fmul2(pk[t], gA);
                acc[1][t] = fmul2(pk[t], gB);
            } else {
                acc[0][t] = ffma2(pk[t], gA, acc[0][t]);
                acc[1][t] = ffma2(pk[t], gB, acc[1][t]);
            }
        }
    }
}

// TM=5/6, cob in GLOBAL memory (stages 8-10), CS=32, via __ldg.
template <int TM, bool FIRST>
__device__ __forceinline__ void acc_i_g(const float* __restrict__ col0,
                                        const ull pv[2],
                                        const ull fx[2], const ull fy[2], const ull fz[2],
                                        ull acc[2][TM]) {
#pragma unroll
    for (int c = 0; c < 3; ++c) {
        const ull fA = (c == 0) ? fx[0] : (c == 1) ? fy[0] : fz[0];
        const ull fB = (c == 0) ? fx[1] : (c == 1) ? fy[1] : fz[1];
        ull gA = fmul2(pv[0], fA);
        ull gB = fmul2(pv[1], fB);
        const float* col = col0 + c * 32;
        float4 v = __ldg(reinterpret_cast<const float4*>(col));
        ull pk[TM];
        pk[0] = pack2(v.x, v.x); pk[1] = pack2(v.y, v.y);
        pk[2] = pack2(v.z, v.z); pk[3] = pack2(v.w, v.w);
        if constexpr (TM == 5) {
            float w = __ldg(col + 4);               // same 128B line as v
            pk[4] = pack2(w, w);
        } else {
            float2 w = __ldg(reinterpret_cast<const float2*>(col + 4));
            pk[4] = pack2(w.x, w.x); pk[5] = pack2(w.y, w.y);
        }
#pragma unroll
        for (int t = 0; t < TM; ++t) {
            if (FIRST && c == 0) {
                acc[0][t] = fmul2(pk[t], gA);
                acc[1][t] = fmul2(pk[t], gB);
            } else {
                acc[0][t] = ffma2(pk[t], gA, acc[0][t]);
                acc[1][t] = ffma2(pk[t], gB, acc[1][t]);
            }
        }
    }
}

// Generic smem-cob stage (l in 3..7).
template <int PL, int TM, int SLOTW>
__device__ __forceinline__ void stageS(const float* __restrict__ cb, const int j,
                                       const ull fx[2], const ull fy[2], const ull fz[2],
                                       const ull* __restrict__ in0, ull* __restrict__ out0) {
    constexpr int NK = PL + 2;
    constexpr int CS = 4 * SLOTW;
    ull acc[2][TM];
    const float* cbj = cb + j * SLOTW;

    {
        ulonglong2 q0 = *reinterpret_cast<const ulonglong2*>(in0);
        ulonglong2 q1 = *reinterpret_cast<const ulonglong2*>(in0 + 22);
        ull pv[2];
        pv[0] = q0.x; pv[1] = q1.x;
        acc_i<TM, SLOTW, CS, true>(cbj, pv, fx, fy, fz, acc);
        pv[0] = q0.y; pv[1] = q1.y;
        acc_i<TM, SLOTW, CS, false>(cbj + 3 * CS, pv, fx, fy, fz, acc);
    }
#pragma unroll
    for (int ii = 2; ii + 1 < PL; ii += 2) {
        ulonglong2 q0 = *reinterpret_cast<const ulonglong2*>(in0 + ii);
        ulonglong2 q1 = *reinterpret_cast<const ulonglong2*>(in0 + 22 + ii);
        ull pv[2];
        pv[0] = q0.x; pv[1] = q1.x;
        acc_i<TM, SLOTW, CS, false>(cbj + 3 * ii * CS, pv, fx, fy, fz, acc);
        pv[0] = q0.y; pv[1] = q1.y;
        acc_i<TM, SLOTW, CS, false>(cbj + 3 * (ii + 1) * CS, pv, fx, fy, fz, acc);
    }
    {
        ull pv[2];
        pv[0] = in0[PL - 1];
        pv[1] = in0[22 + PL - 1];
        acc_i<TM, SLOTW, CS, false>(cbj + 3 * (PL - 1) * CS, pv, fx, fy, fz, acc);
    }
#pragma unroll
    for (int t = 0; t < TM; ++t) {
        const int k = j * TM + t;
        if (k < NK) {
            out0[k] = acc[0][t];
            out0[22 + k] = acc[1][t];
        }
    }
}

// Global-cob stage (l in 8..10), CS=32.
template <int PL, int TM>
__device__ __forceinline__ void stageG(const float* __restrict__ gb, const int j,
                                       const ull fx[2], const ull fy[2], const ull fz[2],
                                       const ull* __restrict__ in0, ull* __restrict__ out0) {
    constexpr int NK = PL + 2;
    ull acc[2][TM];
    const float* cbj = gb + j * 8;

    {
        ulonglong2 q0 = *reinterpret_cast<const ulonglong2*>(in0);
        ulonglong2 q1 = *reinterpret_cast<const ulonglong2*>(in0 + 22);
        ull pv[2];
        pv[0] = q0.x; pv[1] = q1.x;
        acc_i_g<TM, true>(cbj, pv, fx, fy, fz, acc);
        pv[0] = q0.y; pv[1] = q1.y;
        acc_i_g<TM, false>(cbj + 3 * 32, pv, fx, fy, fz, acc);
    }
#pragma unroll
    for (int ii = 2; ii + 1 < PL; ii += 2) {
        ulonglong2 q0 = *reinterpret_cast<const ulonglong2*>(in0 + ii);
        ulonglong2 q1 = *reinterpret_cast<const ulonglong2*>(in0 + 22 + ii);
        ull pv[2];
        pv[0] = q0.x; pv[1] = q1.x;
        acc_i_g<TM, false>(cbj + 3 * ii * 32, pv, fx, fy, fz, acc);
        pv[0] = q0.y; pv[1] = q1.y;
        acc_i_g<TM, false>(cbj + 3 * (ii + 1) * 32, pv, fx, fy, fz, acc);
    }
    {
        ull pv[2];
        pv[0] = in0[PL - 1];
        pv[1] = in0[22 + PL - 1];
        acc_i_g<TM, false>(cbj + 3 * (PL - 1) * 32, pv, fx, fy, fz, acc);
    }
#pragma unroll
    for (int t = 0; t < TM; ++t) {
        const int k = j * TM + t;
        if (k < NK) {
            out0[k] = acc[0][t];
            out0[22 + k] = acc[1][t];
        }
    }
}

// Per-warp copy: warp owns slots [wslot0, wslot0+8) -> 16 pairs (32 points).
template <int NK, int OUTOFF, int POFF>
__device__ __forceinline__ void copy_stage_w(const ull* __restrict__ exu,
                                             float* __restrict__ out,
                                             int base, int rem, int wslot0, int lane) {
    constexpr int TOT = 16 * NK;
#pragma unroll
    for (int i = 0; i < (TOT + 31) / 32; ++i) {
        int e = lane + 32 * i;
        if (e < TOT) {
            int q = e / NK;
            int k = e - q * NK;
            int s8 = q & 7;
            int p = q >> 3;
            ull v = exu[(wslot0 + s8) * EXS + POFF + p * 22 + k];
            float lo, hi;
            asm("mov.b64 {%0, %1}, %2;" : "=f"(lo), "=f"(hi) : "l"(v));
            int ptlo = wslot0 + s8 + 96 * p;
            int pthi = ptlo + 48;
            if (ptlo < rem) __stcs(out + (size_t)(base + ptlo) * 121 + OUTOFF + k, lo);
            if (pthi < rem) __stcs(out + (size_t)(base + pthi) * 121 + OUTOFF + k, hi);
        }
    }
}

__device__ __forceinline__ void copy_hdr_w(const ull* __restrict__ exu,
                                           float* __restrict__ out,
                                           int base, int rem, int wslot0, int lane) {
#pragma unroll
    for (int i = 0; i < 2; ++i) {
        int e = lane + 32 * i;
        int q = e >> 2;
        int k = e & 3;
        int s8 = q & 7;
        int p = q >> 3;
        float lo = 1.0f, hi = 1.0f;
        if (k != 0) {
            ull v = exu[(wslot0 + s8) * EXS + HDR + p * 3 + (k - 1)];
            asm("mov.b64 {%0, %1}, %2;" : "=f"(lo), "=f"(hi) : "l"(v));
        }
        int ptlo = wslot0 + s8 + 96 * p;
        int pthi = ptlo + 48;
        if (ptlo < rem) __stcs(out + (size_t)(base + ptlo) * 121 + k, lo);
        if (pthi < rem) __stcs(out + (size_t)(base + pthi) * 121 + k, hi);
    }
}

__global__ void __launch_bounds__(BLOCK, 4)
harmonic_kernel(const float* __restrict__ pts,
                const float* __restrict__ c1, const float* __restrict__ c2,
                const float* __restrict__ c3, const float* __restrict__ c4,
                const float* __restrict__ c5, const float* __restrict__ c6,
                const float* __restrict__ c7,
                float* __restrict__ out, int N) {
    extern __shared__ float dynf[];
    float* scob = dynf;
    ull* ex = reinterpret_cast<ull*>(dynf + COB_F);

    const int tid = threadIdx.x;
    const int slot = tid >> 2;
    const int j = tid & 3;
    const int lane = tid & 31;
    const int wslot0 = (tid >> 5) * 8;

    if (tid < 16) scob[tid] = (tid < 9) ? c1[tid] : 0.0f;
    load_cob<3, 2, 2>(c2, scob + OFF2, tid);
    load_cob<5, 2, 2>(c3, scob + OFF3, tid);
    load_cob<7, 3, 4>(c4, scob + OFF4, tid);
    load_cob<9, 3, 4>(c5, scob + OFF5, tid);
    load_cob<11, 4, 4>(c6, scob + OFF6, tid);
    load_cob<13, 4, 4>(c7, scob + OFF7, tid);
    __syncthreads();

    const int base = blockIdx.x * TILE;
    int rem = N - base; if (rem > TILE) rem = TILE;

    // 4 points: pair p covers (slot + 96p, slot + 96p + 48)
    ull px[2], py[2], pz[2];
#pragma unroll
    for (int p = 0; p < 2; ++p) {
        int plo = base + slot + 96 * p;
        int phi = plo + 48;
        float xl = 0.f, yl = 0.f, zl = 0.f, xh = 0.f, yh = 0.f, zh = 0.f;
        if (plo < N) { xl = pts[3 * plo]; yl = pts[3 * plo + 1]; zl = pts[3 * plo + 2]; }
        if (phi < N) { xh = pts[3 * phi]; yh = pts[3 * phi + 1]; zh = pts[3 * phi + 2]; }
        px[p] = pack2(xl, xh); py[p] = pack2(yl, yh); pz[p] = pack2(zl, zh);
    }

    ull k0 = pack2(scob[0], scob[0]), k1 = pack2(scob[1], scob[1]), k2 = pack2(scob[2], scob[2]);
    ull k3 = pack2(scob[3], scob[3]), k4 = pack2(scob[4], scob[4]), k5 = pack2(scob[5], scob[5]);
    ull k6 = pack2(scob[6], scob[6]), k7 = pack2(scob[7], scob[7]), k8 = pack2(scob[8], scob[8]);

    ull fx[2], fy[2], fz[2];
#pragma unroll
    for (int p = 0; p < 2; ++p) {
        fx[p] = ffma2(k0, px[p], ffma2(k1, py[p], fmul2(k2, pz[p])));
        fy[p] = ffma2(k3, px[p], ffma2(k4, py[p], fmul2(k5, pz[p])));
        fz[p] = ffma2(k6, px[p], ffma2(k7, py[p], fmul2(k8, pz[p])));
    }

    ull* es = ex + slot * EXS;
    if (j == 0) {
#pragma unroll
        for (int p = 0; p < 2; ++p) {
            es[HDR + p * 3 + 0] = fx[p];
            es[HDR + p * 3 + 1] = fy[p];
            es[HDR + p * 3 + 2] = fz[p];
        }
    }

    // ---- stage l=2 (prev = f1 in registers) -> PH0 ----
    {
        ull acc[2][2];
        const float* cbj = scob + OFF2 + j * 2;
        acc_i<2, 2, 8, true >(cbj,      fx, fx, fy, fz, acc);
        acc_i<2, 2, 8, false>(cbj + 24, fy, fx, fy, fz, acc);
        acc_i<2, 2, 8, false>(cbj + 48, fz, fx, fy, fz, acc);
#pragma unroll
        for (int t = 0; t < 2; ++t) {
            int k = j * 2 + t;
            if (k < 5) { es[PH0 + k] = acc[0][t]; es[PH0 + 22 + k] = acc[1][t]; }
        }
    }
    __syncwarp();

    copy_hdr_w(ex, out, base, rem, wslot0, lane);
    copy_stage_w<5, 4, PH0>(ex, out, base, rem, wslot0, lane);
    stageS<5, 2, 2>(scob + OFF3, j, fx, fy, fz, es + PH0, es + PH1);
    __syncwarp();

    copy_stage_w<7, 9, PH1>(ex, out, base, rem, wslot0, lane);
    stageS<7, 3, 4>(scob + OFF4, j, fx, fy, fz, es + PH1, es + PH0);
    __syncwarp();

    copy_stage_w<9, 16, PH0>(ex, out, base, rem, wslot0, lane);
    stageS<9, 3, 4>(scob + OFF5, j, fx, fy, fz, es + PH0, es + PH1);
    __syncwarp();

    copy_stage_w<11, 25, PH1>(ex, out, base, rem, wslot0, lane);
    stageS<11, 4, 4>(scob + OFF6, j, fx, fy, fz, es + PH1, es + PH0);
    __syncwarp();

    copy_stage_w<13, 36, PH0>(ex, out, base, rem, wslot0, lane);
    stageS<13, 4, 4>(scob + OFF7, j, fx, fy, fz, es + PH0, es + PH1);
    __syncwarp();

    copy_stage_w<15, 49, PH1>(ex, out, base, rem, wslot0, lane);
    stageG<15, 5>(g_cob_big + GB8, j, fx, fy, fz, es + PH1, es + PH0);
    __syncwarp();

    copy_stage_w<17, 64, PH0>(ex, out, base, rem, wslot0, lane);
    stageG<17, 5>(g_cob_big + GB9, j, fx, fy, fz, es + PH0, es + PH1);
    __syncwarp();

    copy_stage_w<19, 81, PH1>(ex, out, base, rem, wslot0, lane);
    stageG<19, 6>(g_cob_big + GB10, j, fx, fy, fz, es + PH1, es + PH0);
    __syncwarp();

    copy_stage_w<21, 100, PH0>(ex, out, base, rem, wslot0, lane);
}

extern "C" void kernel_launch(void* const* d_in, const int* in_sizes, int n_in,
                              void* d_out, int out_size) {
    const float* points = (const float*)d_in[0];
    const int N = in_sizes[0] / 3;
    float* out = (float*)d_out;

    cudaFuncSetAttribute(harmonic_kernel,
                         cudaFuncAttributeMaxDynamicSharedMemorySize, SMEM_BYTES);

    init_cob_big<<<20, 256>>>((const float*)d_in[8], (const float*)d_in[9],
                              (const float*)d_in[10]);

    const int grid = (N + TILE - 1) / TILE;
    harmonic_kernel<<<grid, BLOCK, SMEM_BYTES>>>(
        points,
        (const float*)d_in[1], (const float*)d_in[2], (const float*)d_in[3],
        (const float*)d_in[4], (const float*)d_in[5], (const float*)d_in[6],
        (const float*)d_in[7],
        out, N);
}